// round 15
// baseline (speedup 1.0000x reference)
#include <cuda_runtime.h>
#include <cstdint>

#define BATCH   128
#define NPTS    2048
#define HID     64
#define NSEG    64
#define ROWS    (BATCH * NPTS)          // 262144
#define AGG_ELEMS (BATCH * NSEG * HID)  // 524288 per layer

__device__ float g_h0[(size_t)ROWS * HID];      // 64 MB
__device__ float g_h1[(size_t)ROWS * HID];      // 64 MB
__device__ float g_agg[3 * AGG_ELEMS];          // 6 MB
__device__ float g_P[AGG_ELEMS];                // 2 MB
__device__ int   g_is64;

typedef unsigned long long ull;

static __device__ __forceinline__ ull fma2(ull a, ull b, ull c) {
  ull d;
  asm("fma.rn.f32x2 %0, %1, %2, %3;" : "=l"(d) : "l"(a), "l"(b), "l"(c));
  return d;
}
static __device__ __forceinline__ float u2sum(ull v) {
  return __uint_as_float((unsigned)v) + __uint_as_float((unsigned)(v >> 32));
}

static __device__ __forceinline__ int load_seg(const void* cl, int row, int is64) {
  return is64 ? (int)((const long long*)cl)[row] : ((const int*)cl)[row];
}

// W SMEM fill: interleaved column-pair layout.
// Row cp (= lane) holds, for each k-pair p: [w(2cp)[2p], w(2cp)[2p+1], w(2cp+1)[2p], w(2cp+1)[2p+1]]
template <int K, int RW>
static __device__ __forceinline__ void fill_W(float* sW, const float* W, int tid) {
  for (int idx = tid; idx < 64 * K; idx += 256) {
    int k = idx >> 6, c = idx & 63;
    sW[(c >> 1) * RW + (k >> 1) * 4 + (c & 1) * 2 + (k & 1)] = W[idx];
  }
}

// zero agg buffers + detect cluster dtype (keeps launch count so that
// ncu -s 5 -c 1 lands on the layer-2 kernel).
__global__ void init_kernel(float4* __restrict__ p, const unsigned int* __restrict__ c) {
  int i = blockIdx.x * blockDim.x + threadIdx.x;
  p[i] = make_float4(0.f, 0.f, 0.f, 0.f);
  if (i == 0) {
    unsigned int o = 0;
#pragma unroll
    for (int j = 0; j < 32; ++j) o |= c[2 * j + 1];
    g_is64 = (o == 0) ? 1 : 0;
  }
}

// ---------------------------------------------------------------------------
// Per-segment partial GEMM: P[b,s,:] = agg[b,s,:] @ Whi + bias
// grid = 512: blockIdx.x = b*4 + quarter; each block does 16 segment rows.
// ---------------------------------------------------------------------------
__global__ __launch_bounds__(256) void pre_kernel(
    const float* __restrict__ agg, const float* __restrict__ Whi,
    const float* __restrict__ bias, float* __restrict__ P) {
  __shared__ float sW[32 * 132];
  __shared__ float sA[16 * 64];
  const int tid = threadIdx.x, lane = tid & 31, w = tid >> 5;
  const int b = blockIdx.x >> 2, q = blockIdx.x & 3;

  fill_W<64, 132>(sW, Whi, tid);
  {
    const float4* src = (const float4*)(agg + (size_t)b * 4096 + q * 1024);
    float4* dst = (float4*)sA;
    for (int i = tid; i < 256; i += 256) dst[i] = src[i];
  }
  __syncthreads();

  const float2 bv = *(const float2*)(bias + 2 * lane);
  const float* wp = sW + lane * 132;
  const int r0 = w * 2;

  ull acc[2][2] = {};
#pragma unroll 4
  for (int k4 = 0; k4 < 16; ++k4) {
    ulonglong2 wv0 = *(const ulonglong2*)(wp + 8 * k4);
    ulonglong2 wv1 = *(const ulonglong2*)(wp + 8 * k4 + 4);
#pragma unroll
    for (int r = 0; r < 2; ++r) {
      ulonglong2 av = *(const ulonglong2*)(sA + (r0 + r) * 64 + 4 * k4);
      acc[r][0] = fma2(av.x, wv0.x, acc[r][0]);
      acc[r][1] = fma2(av.x, wv0.y, acc[r][1]);
      acc[r][0] = fma2(av.y, wv1.x, acc[r][0]);
      acc[r][1] = fma2(av.y, wv1.y, acc[r][1]);
    }
  }
#pragma unroll
  for (int r = 0; r < 2; ++r) {
    size_t o = ((size_t)(b << 6) + (q * 16 + r0 + r)) * 64;
    *(float2*)(P + o + 2 * lane) =
        make_float2(u2sum(acc[r][0]) + bv.x, u2sum(acc[r][1]) + bv.y);
  }
}

// ---------------------------------------------------------------------------
// Fused layer: y = A @ W[0:K] (+ bias or + P[b,seg]) ; LN ; *g+beta ; ReLU ;
//   [store h] ; atomicMax scatter into agg.
// Block = 256 thr, 128 rows. Warp owns 16 rows, processed in ONE GEMM pass
// (W amortized over all 16 rows: per k4 = 8 W-wavefronts + 16 A-wavefronts
// against 64 fma2 -> fma pipe is the ceiling, LDS at 75% of it).
// Lane owns cols (2l, 2l+1); f32x2 accumulators packed over K.
// Epilogue runs in two 8-row halves to cap seg/pv register live ranges.
// ---------------------------------------------------------------------------
template <int K, bool WRITE_H, bool HAS_P>
__global__ __launch_bounds__(256) void layer_kernel(
    const float* __restrict__ inA, const float* __restrict__ P,
    const void* __restrict__ cluster,
    const float* __restrict__ W, const float* __restrict__ bias,
    const float* __restrict__ gamma, const float* __restrict__ beta,
    float* __restrict__ outH, float* __restrict__ aggOut) {
  constexpr int RW = (K == 64) ? 132 : 20;
  extern __shared__ char smem_raw[];
  float* sW = (float*)smem_raw;                       // 32*RW
  float* sA = (float*)(smem_raw + 32 * RW * 4);       // 128*K

  const int tid = threadIdx.x, lane = tid & 31, w = tid >> 5;
  const int is64 = g_is64;
  const int rowBase = blockIdx.x * 128;
  const int batch = rowBase >> 11;

  fill_W<K, RW>(sW, W, tid);
  {
    const float4* src = (const float4*)(inA + (size_t)rowBase * K);
    float4* dst = (float4*)sA;
#pragma unroll
    for (int i = tid; i < 128 * K / 4; i += 256) dst[i] = src[i];
  }
  __syncthreads();

  const float2 bv = HAS_P ? make_float2(0.f, 0.f) : *(const float2*)(bias + 2 * lane);
  const float2 gv = *(const float2*)(gamma + 2 * lane);
  const float2 tv = *(const float2*)(beta + 2 * lane);
  const float* wp = sW + lane * RW;
  const int r0 = w * 16;

  ull acc[16][2] = {};
#pragma unroll 2
  for (int k4 = 0; k4 < K / 4; ++k4) {
    ulonglong2 wv0 = *(const ulonglong2*)(wp + 8 * k4);
    ulonglong2 wv1 = *(const ulonglong2*)(wp + 8 * k4 + 4);
#pragma unroll
    for (int r = 0; r < 16; ++r) {
      ulonglong2 av = *(const ulonglong2*)(sA + (r0 + r) * K + 4 * k4);
      acc[r][0] = fma2(av.x, wv0.x, acc[r][0]);
      acc[r][1] = fma2(av.x, wv0.y, acc[r][1]);
      acc[r][0] = fma2(av.y, wv1.x, acc[r][0]);
      acc[r][1] = fma2(av.y, wv1.y, acc[r][1]);
    }
  }

#pragma unroll
  for (int h = 0; h < 2; ++h) {
    const int rb = r0 + h * 8;
    int seg[8];
#pragma unroll
    for (int r = 0; r < 8; ++r) seg[r] = load_seg(cluster, rowBase + rb + r, is64);
    float2 pv[8];
    if (HAS_P) {
#pragma unroll
      for (int r = 0; r < 8; ++r) {
        size_t o = ((size_t)(batch << 6) + seg[r]) * 64;
        pv[r] = *(const float2*)(P + o + 2 * lane);
      }
    }

#pragma unroll
    for (int r = 0; r < 8; ++r) {
      float y0 = u2sum(acc[h * 8 + r][0]) + (HAS_P ? pv[r].x : bv.x);
      float y1 = u2sum(acc[h * 8 + r][1]) + (HAS_P ? pv[r].y : bv.y);
      float s = y0 + y1;
      float q = y0 * y0 + y1 * y1;
#pragma unroll
      for (int off = 16; off; off >>= 1) {
        s += __shfl_xor_sync(0xffffffffu, s, off);
        q += __shfl_xor_sync(0xffffffffu, q, off);
      }
      float mean = s * 0.015625f;
      float var = fmaf(q, 0.015625f, -mean * mean);
      float rstd = rsqrtf(var + 1e-5f);
      float h0 = fmaxf(fmaf((y0 - mean) * rstd, gv.x, tv.x), 0.f);
      float h1 = fmaxf(fmaf((y1 - mean) * rstd, gv.y, tv.y), 0.f);
      if (WRITE_H) {
        *(float2*)(outH + (size_t)(rowBase + rb + r) * 64 + 2 * lane) =
            make_float2(h0, h1);
      }
      int* ab = (int*)(aggOut + ((size_t)(batch << 6) + seg[r]) * 64);
      if (h0 > 0.f) atomicMax(ab + 2 * lane,     __float_as_int(h0));
      if (h1 > 0.f) atomicMax(ab + 2 * lane + 1, __float_as_int(h1));
    }
  }
}

// out[b,s,c] = out[b,s,c+64] = agg2[b,s,c] / max(||agg2[b,:,c]||, 1e-12)
__global__ __launch_bounds__(64) void final_kernel(const float* __restrict__ agg2,
                                                   float* __restrict__ out) {
  const int b = blockIdx.x;
  const int t = threadIdx.x;
  const float* a = agg2 + (size_t)b * NSEG * HID;
  float ss = 0.f;
#pragma unroll
  for (int s = 0; s < NSEG; ++s) {
    float v = a[s * HID + t];
    ss = fmaf(v, v, ss);
  }
  float inv = 1.f / fmaxf(sqrtf(ss), 1e-12f);
  float* o = out + (size_t)b * NSEG * 128;
#pragma unroll
  for (int s = 0; s < NSEG; ++s) {
    float v = a[s * HID + t] * inv;
    o[s * 128 + t]      = v;
    o[s * 128 + 64 + t] = v;
  }
}

// ---------------------------------------------------------------------------
extern "C" void kernel_launch(void* const* d_in, const int* in_sizes, int n_in,
                              void* d_out, int out_size) {
  const float* x  = (const float*)d_in[0];
  const void*  cl = d_in[1];
  const float* W0 = (const float*)d_in[2];
  const float* b0 = (const float*)d_in[3];
  const float* g0 = (const float*)d_in[4];
  const float* t0 = (const float*)d_in[5];
  const float* W1 = (const float*)d_in[6];
  const float* b1 = (const float*)d_in[7];
  const float* g1 = (const float*)d_in[8];
  const float* t1 = (const float*)d_in[9];
  const float* W2 = (const float*)d_in[10];
  const float* b2 = (const float*)d_in[11];
  const float* g2 = (const float*)d_in[12];
  const float* t2 = (const float*)d_in[13];

  void *p_h0 = nullptr, *p_h1 = nullptr, *p_agg = nullptr, *p_P = nullptr;
  cudaGetSymbolAddress(&p_h0, g_h0);
  cudaGetSymbolAddress(&p_h1, g_h1);
  cudaGetSymbolAddress(&p_agg, g_agg);
  cudaGetSymbolAddress(&p_P, g_P);
  float* h0buf = (float*)p_h0;
  float* h1buf = (float*)p_h1;
  float* agg0 = (float*)p_agg;
  float* agg1 = agg0 + AGG_ELEMS;
  float* agg2 = agg0 + 2 * AGG_ELEMS;
  float* P    = (float*)p_P;

  constexpr int SMEM_L0 = (32 * 20 + 128 * 8) * 4;     //  6656 B
  constexpr int SMEM_L  = (32 * 132 + 128 * 64) * 4;   // 49664 B
  cudaFuncSetAttribute(layer_kernel<64, true, true>,
                       cudaFuncAttributeMaxDynamicSharedMemorySize, SMEM_L);
  cudaFuncSetAttribute(layer_kernel<64, false, true>,
                       cudaFuncAttributeMaxDynamicSharedMemorySize, SMEM_L);

  // Launch order matters for ncu (-s 5 -c 1): 6th launch = layer-2 kernel.
  init_kernel<<<(3 * AGG_ELEMS) / 4 / 256, 256>>>((float4*)agg0,
                                                  (const unsigned int*)cl);

  const int blocks = ROWS / 128;  // 2048
  layer_kernel<8, true, false><<<blocks, 256, SMEM_L0>>>(
      x, nullptr, cl, W0, b0, g0, t0, h0buf, agg0);

  pre_kernel<<<BATCH * 4, 256>>>(agg0, W1 + 64 * 64, b1, P);
  layer_kernel<64, true, true><<<blocks, 256, SMEM_L>>>(
      h0buf, P, cl, W1, b1, g1, t1, h1buf, agg1);

  pre_kernel<<<BATCH * 4, 256>>>(agg1, W2 + 64 * 64, b2, P);
  layer_kernel<64, false, true><<<blocks, 256, SMEM_L>>>(
      h1buf, P, cl, W2, b2, g2, t2, nullptr, agg2);

  final_kernel<<<BATCH, 64>>>(agg2, (float*)d_out);
}